// round 1
// baseline (speedup 1.0000x reference)
#include <cuda_runtime.h>

// ---------------------------------------------------------------------------
// DeformConv fused pipeline, fp32 SIMT version (round 1).
// x:(4,256,96,96) w_off:(27,256,3,3) b_off:(27) w:(256,256,3,3) b:(256)
// gamma,beta:(256). out:(4,256,96,96) fp32.
// ---------------------------------------------------------------------------

#define HH 96
#define WW 96
#define SS 9216              // HH*WW
#define NB 4
#define CIN 256
#define COUT 256
#define M_TOTAL (NB * SS)    // 36864 pixels
#define KDIM (9 * CIN)       // 2304

// Scratch (static device memory: allocation-free per harness rules)
__device__ __align__(16) float g_xT[NB * SS * CIN];     // NHWC transpose of x (37.7MB)
__device__ __align__(16) float g_wT[KDIM * COUT];       // wT[tap*256+c][co]   (2.36MB)
__device__ __align__(16) float4 g_pw[9 * M_TOTAL];      // bilinear corner weights * mask
__device__ __align__(16) int4   g_pi[9 * M_TOTAL];      // clipped spatial gather indices
__device__ float g_chsum[COUT];
__device__ float g_chsq[COUT];
__device__ float g_scale[COUT];
__device__ float g_shift[COUT];

// ---------------------------------------------------------------------------
// K0: NCHW -> NHWC transpose of x, and zero the BN accumulators.
// ---------------------------------------------------------------------------
__global__ void k_transpose(const float* __restrict__ x) {
    __shared__ float tile[32][33];
    const int n  = blockIdx.z;
    const int c0 = blockIdx.y * 32;
    const int s0 = blockIdx.x * 32;
    const int tx = threadIdx.x, ty = threadIdx.y;   // 32 x 8

    const float* src = x + (size_t)n * CIN * SS;
#pragma unroll
    for (int i = 0; i < 32; i += 8)
        tile[ty + i][tx] = src[(size_t)(c0 + ty + i) * SS + (s0 + tx)];
    __syncthreads();
    float* dst = g_xT + (size_t)n * SS * CIN;
#pragma unroll
    for (int i = 0; i < 32; i += 8)
        dst[(size_t)(s0 + ty + i) * CIN + (c0 + tx)] = tile[tx][ty + i];

    if (blockIdx.x == 0 && blockIdx.y == 0 && n == 0) {
        int id = ty * 32 + tx;
        if (id < COUT) { g_chsum[id] = 0.0f; g_chsq[id] = 0.0f; }
    }
}

// ---------------------------------------------------------------------------
// K0b: weight transpose: g_wT[(tap*256+c)*256 + co] = w[co][c][tap]
// ---------------------------------------------------------------------------
__global__ void k_wtrans(const float* __restrict__ w) {
    const int kk = blockIdx.x;          // 0..2303
    const int co = threadIdx.x;         // 0..255
    const int c = kk & 255, tap = kk >> 8;
    g_wT[(size_t)kk * COUT + co] = w[(size_t)co * KDIM + c * 9 + tap];
}

// ---------------------------------------------------------------------------
// K1: offset conv (Cin=256 -> 27, 3x3, pad 1) + bilinear parameter precompute.
// 144 blocks x 128 threads, 2 pixels per thread.
// ---------------------------------------------------------------------------
__device__ __forceinline__ void write_params(int p, int h, int w, const float* om) {
#pragma unroll
    for (int k = 0; k < 9; k++) {
        float dy = om[k];
        float dx = om[9 + k];
        float mm = 1.0f / (1.0f + __expf(-om[18 + k]));
        float kyf = (float)(k / 3 - 1);
        float kxf = (float)(k % 3 - 1);
        float py = (dy + (float)h) + kyf;
        float px = (dx + (float)w) + kxf;
        float y0f = floorf(py), x0f = floorf(px);
        float ly = py - y0f, lx = px - x0f;
        float vy0 = (y0f >= 0.0f && y0f <= 95.0f) ? 1.0f : 0.0f;
        float vy1 = (y0f + 1.0f >= 0.0f && y0f + 1.0f <= 95.0f) ? 1.0f : 0.0f;
        float vx0 = (x0f >= 0.0f && x0f <= 95.0f) ? 1.0f : 0.0f;
        float vx1 = (x0f + 1.0f >= 0.0f && x0f + 1.0f <= 95.0f) ? 1.0f : 0.0f;
        int iy0 = (int)fminf(fmaxf(y0f, 0.0f), 95.0f);
        int iy1 = (int)fminf(fmaxf(y0f + 1.0f, 0.0f), 95.0f);
        int ix0 = (int)fminf(fmaxf(x0f, 0.0f), 95.0f);
        int ix1 = (int)fminf(fmaxf(x0f + 1.0f, 0.0f), 95.0f);
        float w00 = (1.0f - ly) * (1.0f - lx) * vy0 * vx0 * mm;
        float w01 = (1.0f - ly) * lx          * vy0 * vx1 * mm;
        float w10 = ly          * (1.0f - lx) * vy1 * vx0 * mm;
        float w11 = ly          * lx          * vy1 * vx1 * mm;
        g_pw[k * M_TOTAL + p] = make_float4(w00, w01, w10, w11);
        g_pi[k * M_TOTAL + p] = make_int4(iy0 * WW + ix0, iy0 * WW + ix1,
                                          iy1 * WW + ix0, iy1 * WW + ix1);
    }
}

__global__ __launch_bounds__(128) void k_offset(const float* __restrict__ w_off,
                                                const float* __restrict__ b_off) {
    __shared__ __align__(16) float wsm[27 * 256];   // [o][c] for current tap
    const int t = threadIdx.x;
    const int pA = blockIdx.x * 256 + t;
    const int pB = pA + 128;

    const int nA = pA / SS, sA = pA % SS, hA = sA / WW, wA = sA % WW;
    const int nB = pB / SS, sB = pB % SS, hB = sB / WW, wB = sB % WW;

    float accA[27], accB[27];
#pragma unroll
    for (int o = 0; o < 27; o++) { accA[o] = 0.0f; accB[o] = 0.0f; }

    for (int tap = 0; tap < 9; tap++) {
        __syncthreads();
        for (int idx = t; idx < 27 * 256; idx += 128) {
            int o = idx >> 8, c = idx & 255;
            wsm[idx] = w_off[(size_t)o * KDIM + c * 9 + tap];
        }
        __syncthreads();

        const int ky = tap / 3 - 1, kx = tap % 3 - 1;
        const int ya = hA + ky, xa = wA + kx;
        const int yb = hB + ky, xb = wB + kx;
        const bool va = (ya >= 0 && ya < HH && xa >= 0 && xa < WW);
        const bool vb = (yb >= 0 && yb < HH && xb >= 0 && xb < WW);
        if (!(va || vb)) continue;

        const float* pa = g_xT + (size_t)(nA * SS + ya * WW + xa) * CIN;
        const float* pb = g_xT + (size_t)(nB * SS + yb * WW + xb) * CIN;

        for (int c = 0; c < 256; c += 4) {
            float4 x4a = va ? *(const float4*)(pa + c) : make_float4(0, 0, 0, 0);
            float4 x4b = vb ? *(const float4*)(pb + c) : make_float4(0, 0, 0, 0);
#pragma unroll
            for (int o = 0; o < 27; o++) {
                float4 w4 = *(const float4*)&wsm[o * 256 + c];
                accA[o] += x4a.x * w4.x + x4a.y * w4.y + x4a.z * w4.z + x4a.w * w4.w;
                accB[o] += x4b.x * w4.x + x4b.y * w4.y + x4b.z * w4.z + x4b.w * w4.w;
            }
        }
    }

#pragma unroll
    for (int o = 0; o < 27; o++) { float bo = b_off[o]; accA[o] += bo; accB[o] += bo; }
    write_params(pA, hA, wA, accA);
    write_params(pB, hB, wB, accB);
}

// ---------------------------------------------------------------------------
// K2: GEMM with gather-on-the-fly A.
//   M=36864 (pixels), N=256 (couts), K=2304 (tap*256+c).
//   Mtile=128, Ntile=256, Ktile=16. 288 blocks x 512 threads, 4x16 microtile.
//   Fused: +b, write y to d_out (pre-BN), per-channel sum/sumsq atomics.
// ---------------------------------------------------------------------------
__global__ __launch_bounds__(512, 1) void k_gemm(const float* __restrict__ bvec,
                                                 float* __restrict__ out) {
    __shared__ __align__(16) float As[16][128];   // [k_local][pixel]
    __shared__ __align__(16) float Bs[16][256];   // [k_local][cout]

    const int t = threadIdx.x;
    const int m0 = blockIdx.x * 128;              // 9216 % 128 == 0 -> single n per block
    const int n = m0 / SS;
    const int sbase = m0 % SS;
    const float* xbase = g_xT + (size_t)n * SS * CIN;

    // gather assignment
    const int gpix = t & 127;
    const int gcl  = (t >> 7) * 4;                // channel offset within 16-chunk (0,4,8,12)
    // compute assignment
    const int px0   = (t >> 4) * 4;               // pixel micro base (0..124)
    const int cbase = (t & 15) * 4;               // cout cluster base

    float acc[4][16];
#pragma unroll
    for (int p = 0; p < 4; p++)
#pragma unroll
        for (int j = 0; j < 16; j++) acc[p][j] = 0.0f;

    for (int tap = 0; tap < 9; tap++) {
        const float4 pm = g_pw[tap * M_TOTAL + m0 + gpix];
        const int4   ii = g_pi[tap * M_TOTAL + m0 + gpix];
        const float* b00 = xbase + (size_t)ii.x * CIN;
        const float* b01 = xbase + (size_t)ii.y * CIN;
        const float* b10 = xbase + (size_t)ii.z * CIN;
        const float* b11 = xbase + (size_t)ii.w * CIN;

        for (int c0 = 0; c0 < 256; c0 += 16) {
            __syncthreads();   // previous tile fully consumed
            // --- load B tile (16 x 256) ---
#pragma unroll
            for (int r = 0; r < 2; r++) {
                int idx = t + 512 * r;            // 0..1023 float4 slots
                int row = idx >> 6, q = idx & 63;
                *(float4*)&Bs[row][q * 4] =
                    *(const float4*)&g_wT[(size_t)(tap * 256 + c0 + row) * COUT + q * 4];
            }
            // --- gather A tile: 4 channels of one pixel ---
            {
                int c = c0 + gcl;
                float4 v00 = *(const float4*)(b00 + c);
                float4 v01 = *(const float4*)(b01 + c);
                float4 v10 = *(const float4*)(b10 + c);
                float4 v11 = *(const float4*)(b11 + c);
                As[gcl + 0][gpix] = pm.x * v00.x + pm.y * v01.x + pm.z * v10.x + pm.w * v11.x;
                As[gcl + 1][gpix] = pm.x * v00.y + pm.y * v01.y + pm.z * v10.y + pm.w * v11.y;
                As[gcl + 2][gpix] = pm.x * v00.z + pm.y * v01.z + pm.z * v10.z + pm.w * v11.z;
                As[gcl + 3][gpix] = pm.x * v00.w + pm.y * v01.w + pm.z * v10.w + pm.w * v11.w;
            }
            __syncthreads();
            // --- compute ---
#pragma unroll
            for (int kk = 0; kk < 16; kk++) {
                float4 a4 = *(const float4*)&As[kk][px0];
#pragma unroll
                for (int i = 0; i < 4; i++) {
                    float4 b4 = *(const float4*)&Bs[kk][cbase + 64 * i];
                    acc[0][i * 4 + 0] += a4.x * b4.x;
                    acc[0][i * 4 + 1] += a4.x * b4.y;
                    acc[0][i * 4 + 2] += a4.x * b4.z;
                    acc[0][i * 4 + 3] += a4.x * b4.w;
                    acc[1][i * 4 + 0] += a4.y * b4.x;
                    acc[1][i * 4 + 1] += a4.y * b4.y;
                    acc[1][i * 4 + 2] += a4.y * b4.z;
                    acc[1][i * 4 + 3] += a4.y * b4.w;
                    acc[2][i * 4 + 0] += a4.z * b4.x;
                    acc[2][i * 4 + 1] += a4.z * b4.y;
                    acc[2][i * 4 + 2] += a4.z * b4.z;
                    acc[2][i * 4 + 3] += a4.z * b4.w;
                    acc[3][i * 4 + 0] += a4.w * b4.x;
                    acc[3][i * 4 + 1] += a4.w * b4.y;
                    acc[3][i * 4 + 2] += a4.w * b4.z;
                    acc[3][i * 4 + 3] += a4.w * b4.w;
                }
            }
        }
    }

    // epilogue: +b, write pre-BN y to out, accumulate channel stats
    const size_t obase = (size_t)n * COUT * SS + sbase + px0;
#pragma unroll
    for (int i = 0; i < 4; i++) {
#pragma unroll
        for (int j = 0; j < 4; j++) {
            int co = cbase + 64 * i + j;
            float bb = bvec[co];
            float s = 0.0f, q = 0.0f;
#pragma unroll
            for (int p = 0; p < 4; p++) {
                float v = acc[p][i * 4 + j] + bb;
                out[obase + (size_t)co * SS + p] = v;
                s += v;
                q += v * v;
            }
            atomicAdd(&g_chsum[co], s);
            atomicAdd(&g_chsq[co], q);
        }
    }
}

// ---------------------------------------------------------------------------
// K3: BN statistics -> per-channel scale/shift
// ---------------------------------------------------------------------------
__global__ void k_stats(const float* __restrict__ gamma, const float* __restrict__ beta) {
    const int co = threadIdx.x;
    const float inv = 1.0f / (float)M_TOTAL;
    float mean = g_chsum[co] * inv;
    float var = g_chsq[co] * inv - mean * mean;
    float sc = gamma[co] * rsqrtf(var + 1e-5f);
    g_scale[co] = sc;
    g_shift[co] = beta[co] - mean * sc;
}

// ---------------------------------------------------------------------------
// K4: normalize + ReLU in place
// ---------------------------------------------------------------------------
__global__ void k_norm(float* __restrict__ out) {
    const size_t i = ((size_t)blockIdx.x * blockDim.x + threadIdx.x) * 4;
    const int co = (int)((i / SS) & 255);
    float sc = g_scale[co], sh = g_shift[co];
    float4 v = *(float4*)(out + i);
    v.x = fmaxf(v.x * sc + sh, 0.0f);
    v.y = fmaxf(v.y * sc + sh, 0.0f);
    v.z = fmaxf(v.z * sc + sh, 0.0f);
    v.w = fmaxf(v.w * sc + sh, 0.0f);
    *(float4*)(out + i) = v;
}

// ---------------------------------------------------------------------------
extern "C" void kernel_launch(void* const* d_in, const int* in_sizes, int n_in,
                              void* d_out, int out_size) {
    (void)in_sizes; (void)n_in; (void)out_size;
    const float* x     = (const float*)d_in[0];
    const float* w_off = (const float*)d_in[1];
    const float* b_off = (const float*)d_in[2];
    const float* w     = (const float*)d_in[3];
    const float* b     = (const float*)d_in[4];
    const float* gamma = (const float*)d_in[5];
    const float* beta  = (const float*)d_in[6];
    float* out = (float*)d_out;

    k_transpose<<<dim3(SS / 32, CIN / 32, NB), dim3(32, 8)>>>(x);
    k_wtrans<<<KDIM, COUT>>>(w);
    k_offset<<<M_TOTAL / 256, 128>>>(w_off, b_off);
    k_gemm<<<M_TOTAL / 128, 512>>>(b, out);
    k_stats<<<1, COUT>>>(gamma, beta);
    k_norm<<<(NB * COUT * SS) / (256 * 4), 256>>>(out);
}

// round 3
// speedup vs baseline: 1.9484x; 1.9484x over previous
#include <cuda_runtime.h>
#include <cuda_bf16.h>

// ---------------------------------------------------------------------------
// DeformConv fused pipeline, round 3: HMMA (mma.sync bf16x3) GEMM.
// tcgen05 is not assemblable under this harness (.target sm_103, no 'a'),
// so the tensor pipe is driven via mma.sync.m16n8k16.bf16 + ldmatrix.
// ---------------------------------------------------------------------------

#define HH 96
#define WW 96
#define SS 9216
#define NB 4
#define CIN 256
#define COUT 256
#define M_TOTAL (NB * SS)      // 36864
#define KDIM (9 * CIN)         // 2304
#define NKT 72                 // 2304 / 32 k-tiles
#define NK16 144               // 2304 / 16

// Scratch (static device memory)
__device__ __align__(16) float g_xT[NB * SS * CIN];          // NHWC x (37.7MB)
__device__ __align__(16) unsigned g_wF[NK16 * 2 * 8 * 32 * 8]; // B frags (2.36MB)
__device__ __align__(16) float4 g_pw[9 * M_TOTAL];           // corner weights * mask
__device__ __align__(16) int4   g_pi[9 * M_TOTAL];           // clipped gather indices
__device__ float g_scale[COUT];
__device__ float g_shift[COUT];

// ---------------- asm helpers (baseline PTX, sm_80-class) ----------------
__device__ __forceinline__ unsigned smem_u32(const void* p) {
    unsigned a;
    asm("{ .reg .u64 t; cvta.to.shared.u64 t, %1; cvt.u32.u64 %0, t; }" : "=r"(a) : "l"(p));
    return a;
}

#define LDSM_X4(r, a) \
    asm volatile("ldmatrix.sync.aligned.m8n8.x4.shared.b16 {%0,%1,%2,%3}, [%4];" \
                 : "=r"((r)[0]), "=r"((r)[1]), "=r"((r)[2]), "=r"((r)[3]) : "r"(a))

#define MMA_BF16(d, a, b) \
    asm volatile("mma.sync.aligned.m16n8k16.row.col.f32.bf16.bf16.f32 " \
                 "{%0,%1,%2,%3}, {%4,%5,%6,%7}, {%8,%9}, {%0,%1,%2,%3};" \
                 : "+f"((d)[0]), "+f"((d)[1]), "+f"((d)[2]), "+f"((d)[3]) \
                 : "r"((a)[0]), "r"((a)[1]), "r"((a)[2]), "r"((a)[3]), \
                   "r"((b)[0]), "r"((b)[1]))

__device__ __forceinline__ unsigned pack_bf16(float x0, float x1) {
    __nv_bfloat16 h0 = __float2bfloat16(x0);
    __nv_bfloat16 h1 = __float2bfloat16(x1);
    return (unsigned)__bfloat16_as_ushort(h0) | ((unsigned)__bfloat16_as_ushort(h1) << 16);
}

// ---------------------------------------------------------------------------
// K0: NCHW -> NHWC transpose of x
// ---------------------------------------------------------------------------
__global__ void k_transpose(const float* __restrict__ x) {
    __shared__ float tile[32][33];
    const int n  = blockIdx.z;
    const int c0 = blockIdx.y * 32;
    const int s0 = blockIdx.x * 32;
    const int tx = threadIdx.x, ty = threadIdx.y;
    const float* src = x + (size_t)n * CIN * SS;
#pragma unroll
    for (int i = 0; i < 32; i += 8)
        tile[ty + i][tx] = src[(size_t)(c0 + ty + i) * SS + (s0 + tx)];
    __syncthreads();
    float* dst = g_xT + (size_t)n * SS * CIN;
#pragma unroll
    for (int i = 0; i < 32; i += 8)
        dst[(size_t)(s0 + ty + i) * CIN + (c0 + tx)] = tile[tx][ty + i];
}

// ---------------------------------------------------------------------------
// K0b: build B fragments directly in mma.sync .col register layout.
// Index: (((K16*2 + split)*8 + coutblk)*32 + lane)*8 + r,  r = nfrag*2 + rr.
// reg = {B[k][n], B[k+1][n]} packed bf16x2, k = K16*16 + (lane&3)*2 + rr*8,
// n = coutblk*32 + nfrag*8 + (lane>>2).  B[k][n] = w[n][c][tap], k = tap*256+c.
// ---------------------------------------------------------------------------
__global__ void k_wprep(const float* __restrict__ w) {
    const int T = blockIdx.x * 256 + threadIdx.x;   // 0 .. 589823
    const int r  = T & 7;
    const int l  = (T >> 3) & 31;
    const int cb = (T >> 8) & 7;
    const int s  = (T >> 11) & 1;
    const int K  = T >> 12;                          // 0..143
    const int f  = r >> 1, rr = r & 1;
    const int n  = cb * 32 + f * 8 + (l >> 2);
    const int kk = K * 16 + (l & 3) * 2 + rr * 8;

    float v0, v1;
    {
        int tap = kk >> 8, c = kk & 255;
        v0 = w[(size_t)n * KDIM + c * 9 + tap];
        tap = (kk + 1) >> 8; c = (kk + 1) & 255;
        v1 = w[(size_t)n * KDIM + c * 9 + tap];
    }
    if (s == 0) {
        g_wF[T] = pack_bf16(__bfloat162float(__float2bfloat16(v0)),
                            __bfloat162float(__float2bfloat16(v1)));
    } else {
        float h0 = __bfloat162float(__float2bfloat16(v0));
        float h1 = __bfloat162float(__float2bfloat16(v1));
        g_wF[T] = pack_bf16(v0 - h0, v1 - h1);
    }
}

// ---------------------------------------------------------------------------
// K1: offset conv (256->27, 3x3, pad1) + bilinear parameter precompute
// ---------------------------------------------------------------------------
__device__ __forceinline__ void write_params(int p, int h, int w, const float* om) {
#pragma unroll
    for (int k = 0; k < 9; k++) {
        float dy = om[k];
        float dx = om[9 + k];
        float mm = 1.0f / (1.0f + __expf(-om[18 + k]));
        float kyf = (float)(k / 3 - 1);
        float kxf = (float)(k % 3 - 1);
        float py = (dy + (float)h) + kyf;
        float px = (dx + (float)w) + kxf;
        float y0f = floorf(py), x0f = floorf(px);
        float ly = py - y0f, lx = px - x0f;
        float vy0 = (y0f >= 0.0f && y0f <= 95.0f) ? 1.0f : 0.0f;
        float vy1 = (y0f + 1.0f >= 0.0f && y0f + 1.0f <= 95.0f) ? 1.0f : 0.0f;
        float vx0 = (x0f >= 0.0f && x0f <= 95.0f) ? 1.0f : 0.0f;
        float vx1 = (x0f + 1.0f >= 0.0f && x0f + 1.0f <= 95.0f) ? 1.0f : 0.0f;
        int iy0 = (int)fminf(fmaxf(y0f, 0.0f), 95.0f);
        int iy1 = (int)fminf(fmaxf(y0f + 1.0f, 0.0f), 95.0f);
        int ix0 = (int)fminf(fmaxf(x0f, 0.0f), 95.0f);
        int ix1 = (int)fminf(fmaxf(x0f + 1.0f, 0.0f), 95.0f);
        float w00 = (1.0f - ly) * (1.0f - lx) * vy0 * vx0 * mm;
        float w01 = (1.0f - ly) * lx          * vy0 * vx1 * mm;
        float w10 = ly          * (1.0f - lx) * vy1 * vx0 * mm;
        float w11 = ly          * lx          * vy1 * vx1 * mm;
        g_pw[k * M_TOTAL + p] = make_float4(w00, w01, w10, w11);
        g_pi[k * M_TOTAL + p] = make_int4(iy0 * WW + ix0, iy0 * WW + ix1,
                                          iy1 * WW + ix0, iy1 * WW + ix1);
    }
}

__global__ __launch_bounds__(128) void k_offset(const float* __restrict__ w_off,
                                                const float* __restrict__ b_off) {
    __shared__ __align__(16) float wsm[27 * 256];
    const int t = threadIdx.x;
    const int pA = blockIdx.x * 256 + t;
    const int pB = pA + 128;
    const int nA = pA / SS, sA = pA % SS, hA = sA / WW, wA = sA % WW;
    const int nB = pB / SS, sB = pB % SS, hB = sB / WW, wB = sB % WW;

    float accA[27], accB[27];
#pragma unroll
    for (int o = 0; o < 27; o++) { accA[o] = 0.0f; accB[o] = 0.0f; }

    for (int tap = 0; tap < 9; tap++) {
        __syncthreads();
        for (int idx = t; idx < 27 * 256; idx += 128) {
            int o = idx >> 8, c = idx & 255;
            wsm[idx] = w_off[(size_t)o * KDIM + c * 9 + tap];
        }
        __syncthreads();

        const int ky = tap / 3 - 1, kx = tap % 3 - 1;
        const int ya = hA + ky, xa = wA + kx;
        const int yb = hB + ky, xb = wB + kx;
        const bool va = (ya >= 0 && ya < HH && xa >= 0 && xa < WW);
        const bool vb = (yb >= 0 && yb < HH && xb >= 0 && xb < WW);
        if (!(va || vb)) continue;

        const float* pa = g_xT + (size_t)(nA * SS + ya * WW + xa) * CIN;
        const float* pb = g_xT + (size_t)(nB * SS + yb * WW + xb) * CIN;

        for (int c = 0; c < 256; c += 4) {
            float4 x4a = va ? *(const float4*)(pa + c) : make_float4(0, 0, 0, 0);
            float4 x4b = vb ? *(const float4*)(pb + c) : make_float4(0, 0, 0, 0);
#pragma unroll
            for (int o = 0; o < 27; o++) {
                float4 w4 = *(const float4*)&wsm[o * 256 + c];
                accA[o] += x4a.x * w4.x + x4a.y * w4.y + x4a.z * w4.z + x4a.w * w4.w;
                accB[o] += x4b.x * w4.x + x4b.y * w4.y + x4b.z * w4.z + x4b.w * w4.w;
            }
        }
    }
#pragma unroll
    for (int o = 0; o < 27; o++) { float bo = b_off[o]; accA[o] += bo; accB[o] += bo; }
    write_params(pA, hA, wA, accA);
    write_params(pB, hB, wB, accB);
}

// ---------------------------------------------------------------------------
// K2: HMMA GEMM, bf16x3. Mtile=128, Ntile=128, Ktile=32. 256 thr (8 warps:
// 2 m-warps x 4 n-warps, warp tile 64x32). Grid (288, 2).
// A gathered into double-buffered smem (80B rows, conflict-free ldmatrix);
// B read as prebuilt fragments straight from L2.
// ---------------------------------------------------------------------------
__global__ __launch_bounds__(256, 2) void k_gemm(const float* __restrict__ bvec,
                                                 float* __restrict__ out) {
    __shared__ __nv_bfloat16 Asm[2][2][128][40];   // [buf][split][pix][ch] 40KB

    const int tid = threadIdx.x;
    const int wid = tid >> 5;
    const int lane = tid & 31;
    const int wm = wid >> 2;            // 0..1
    const int wn = wid & 3;             // 0..3
    const int blkN = blockIdx.y;        // 0..1
    const int cbi = blkN * 4 + wn;      // cout block 0..7

    const int m0 = blockIdx.x * 128;
    const int n = m0 / SS;
    const int sb = m0 % SS;
    const float* xbase = g_xT + (size_t)n * SS * CIN;

    // gather role
    const int pix = tid >> 1;           // 0..127
    const int h   = tid & 1;            // 16-channel half of the 32-ch ktile

    // ldmatrix lane addressing
    const int lr = (lane & 7) + ((lane >> 3) & 1) * 8;   // row within m16
    const int lc = (lane >> 4) * 16;                     // byte col within k16
    const unsigned Abase = smem_u32(&Asm[0][0][0][0]);

    float acc[4][4][4];
#pragma unroll
    for (int a = 0; a < 4; a++)
#pragma unroll
        for (int b = 0; b < 4; b++)
#pragma unroll
            for (int c = 0; c < 4; c++) acc[a][b][c] = 0.0f;

    float4 pm; int4 ii;
    const float *q00 = xbase, *q01 = xbase, *q10 = xbase, *q11 = xbase;

    auto gather = [&](int t, int buf) {
        const int tap = t >> 3, sub = t & 7;
        if ((t & 7) == 0) {
            pm = g_pw[tap * M_TOTAL + m0 + pix];
            ii = g_pi[tap * M_TOTAL + m0 + pix];
            q00 = xbase + (size_t)ii.x * CIN;
            q01 = xbase + (size_t)ii.y * CIN;
            q10 = xbase + (size_t)ii.z * CIN;
            q11 = xbase + (size_t)ii.w * CIN;
        }
        const int cb = sub * 32 + h * 16;
        float a[16];
#pragma unroll
        for (int j = 0; j < 4; j++) {
            float4 v00 = *(const float4*)(q00 + cb + 4 * j);
            float4 v01 = *(const float4*)(q01 + cb + 4 * j);
            float4 v10 = *(const float4*)(q10 + cb + 4 * j);
            float4 v11 = *(const float4*)(q11 + cb + 4 * j);
            a[4 * j + 0] = pm.x * v00.x + pm.y * v01.x + pm.z * v10.x + pm.w * v11.x;
            a[4 * j + 1] = pm.x * v00.y + pm.y * v01.y + pm.z * v10.y + pm.w * v11.y;
            a[4 * j + 2] = pm.x * v00.z + pm.y * v01.z + pm.z * v10.z + pm.w * v11.z;
            a[4 * j + 3] = pm.x * v00.w + pm.y * v01.w + pm.z * v10.w + pm.w * v11.w;
        }
        unsigned hh[8], ll[8];
#pragma unroll
        for (int j = 0; j < 8; j++) {
            float x0 = a[2 * j], x1 = a[2 * j + 1];
            float h0 = __bfloat162float(__float2bfloat16(x0));
            float h1 = __bfloat162float(__float2bfloat16(x1));
            hh[j] = pack_bf16(h0, h1);
            ll[j] = pack_bf16(x0 - h0, x1 - h1);
        }
        uint4* dh = (uint4*)&Asm[buf][0][pix][h * 16];
        dh[0] = make_uint4(hh[0], hh[1], hh[2], hh[3]);
        dh[1] = make_uint4(hh[4], hh[5], hh[6], hh[7]);
        uint4* dl = (uint4*)&Asm[buf][1][pix][h * 16];
        dl[0] = make_uint4(ll[0], ll[1], ll[2], ll[3]);
        dl[1] = make_uint4(ll[4], ll[5], ll[6], ll[7]);
    };

    auto compute = [&](int t, int buf) {
        const unsigned base0 = Abase + (unsigned)(buf * 2) * (128 * 40 * 2);
        const unsigned base1 = base0 + 128 * 40 * 2;
#pragma unroll
        for (int q = 0; q < 2; q++) {
            const int K = t * 2 + q;
            const uint4* bph = (const uint4*)(g_wF + (((size_t)(K * 2 + 0) * 8 + cbi) * 32 + lane) * 8);
            const uint4* bpl = (const uint4*)(g_wF + (((size_t)(K * 2 + 1) * 8 + cbi) * 32 + lane) * 8);
            uint4 h0 = bph[0], h1 = bph[1];
            uint4 l0 = bpl[0], l1 = bpl[1];
            unsigned Bh[8] = {h0.x, h0.y, h0.z, h0.w, h1.x, h1.y, h1.z, h1.w};
            unsigned Bl[8] = {l0.x, l0.y, l0.z, l0.w, l1.x, l1.y, l1.z, l1.w};
#pragma unroll
            for (int mt = 0; mt < 4; mt++) {
                const unsigned ro = (unsigned)(wm * 64 + mt * 16 + lr) * 80 + q * 32 + lc;
                unsigned ah[4], al[4];
                LDSM_X4(ah, base0 + ro);
                LDSM_X4(al, base1 + ro);
#pragma unroll
                for (int f = 0; f < 4; f++) {
                    MMA_BF16(acc[mt][f], ah, &Bh[2 * f]);
                    MMA_BF16(acc[mt][f], ah, &Bl[2 * f]);
                    MMA_BF16(acc[mt][f], al, &Bh[2 * f]);
                }
            }
        }
    };

    gather(0, 0);
    __syncthreads();
#pragma unroll 1
    for (int t = 0; t < NKT; t++) {
        if (t + 1 < NKT) gather(t + 1, (t + 1) & 1);
        compute(t, t & 1);
        __syncthreads();
    }

    // epilogue: +bias, write pre-BN y
#pragma unroll
    for (int f = 0; f < 4; f++) {
        const int co = blkN * 128 + wn * 32 + f * 8 + (lane & 3) * 2;
        const float b0 = __ldg(&bvec[co]);
        const float b1 = __ldg(&bvec[co + 1]);
        float* o0 = out + ((size_t)n * COUT + co) * SS + sb + wm * 64 + (lane >> 2);
        float* o1 = o0 + SS;
#pragma unroll
        for (int mt = 0; mt < 4; mt++) {
            const int r = mt * 16;
            o0[r]     = acc[mt][f][0] + b0;
            o1[r]     = acc[mt][f][1] + b1;
            o0[r + 8] = acc[mt][f][2] + b0;
            o1[r + 8] = acc[mt][f][3] + b1;
        }
    }
}

// ---------------------------------------------------------------------------
// K3: BN statistics from y (one block per channel)
// ---------------------------------------------------------------------------
__global__ void k_stats(const float* __restrict__ y, const float* __restrict__ gamma,
                        const float* __restrict__ beta) {
    const int co = blockIdx.x;
    const int t = threadIdx.x;   // 256
    float s = 0.0f, q = 0.0f;
#pragma unroll
    for (int n = 0; n < NB; n++) {
        const float* p = y + ((size_t)n * COUT + co) * SS;
#pragma unroll
        for (int i = 0; i < 9; i++) {
            float4 v = *(const float4*)(p + t * 4 + i * 1024);
            s += v.x + v.y + v.z + v.w;
            q += v.x * v.x + v.y * v.y + v.z * v.z + v.w * v.w;
        }
    }
#pragma unroll
    for (int o = 16; o; o >>= 1) {
        s += __shfl_xor_sync(~0u, s, o);
        q += __shfl_xor_sync(~0u, q, o);
    }
    __shared__ float ssm[8], qsm[8];
    if ((t & 31) == 0) { ssm[t >> 5] = s; qsm[t >> 5] = q; }
    __syncthreads();
    if (t == 0) {
        s = 0.0f; q = 0.0f;
#pragma unroll
        for (int i = 0; i < 8; i++) { s += ssm[i]; q += qsm[i]; }
        float mean = s / (float)M_TOTAL;
        float var = q / (float)M_TOTAL - mean * mean;
        float sc = gamma[co] * rsqrtf(var + 1e-5f);
        g_scale[co] = sc;
        g_shift[co] = beta[co] - mean * sc;
    }
}

// ---------------------------------------------------------------------------
// K4: normalize + ReLU in place
// ---------------------------------------------------------------------------
__global__ void k_norm(float* __restrict__ out) {
    const size_t i = ((size_t)blockIdx.x * blockDim.x + threadIdx.x) * 4;
    const int co = (int)((i / SS) & 255);
    float sc = g_scale[co], sh = g_shift[co];
    float4 v = *(float4*)(out + i);
    v.x = fmaxf(v.x * sc + sh, 0.0f);
    v.y = fmaxf(v.y * sc + sh, 0.0f);
    v.z = fmaxf(v.z * sc + sh, 0.0f);
    v.w = fmaxf(v.w * sc + sh, 0.0f);
    *(float4*)(out + i) = v;
}

// ---------------------------------------------------------------------------
extern "C" void kernel_launch(void* const* d_in, const int* in_sizes, int n_in,
                              void* d_out, int out_size) {
    (void)in_sizes; (void)n_in; (void)out_size;
    const float* x     = (const float*)d_in[0];
    const float* w_off = (const float*)d_in[1];
    const float* b_off = (const float*)d_in[2];
    const float* w     = (const float*)d_in[3];
    const float* b     = (const float*)d_in[4];
    const float* gamma = (const float*)d_in[5];
    const float* beta  = (const float*)d_in[6];
    float* out = (float*)d_out;

    k_transpose<<<dim3(SS / 32, CIN / 32, NB), dim3(32, 8)>>>(x);
    k_wprep<<<2304, 256>>>(w);
    k_offset<<<M_TOTAL / 256, 128>>>(w_off, b_off);
    k_gemm<<<dim3(M_TOTAL / 128, 2), 256>>>(b, out);
    k_stats<<<COUT, 256>>>(out, gamma, beta);
    k_norm<<<(NB * COUT * SS) / (256 * 4), 256>>>(out);
}

// round 4
// speedup vs baseline: 3.2815x; 1.6841x over previous
#include <cuda_runtime.h>
#include <cuda_bf16.h>

// ---------------------------------------------------------------------------
// DeformConv fused pipeline, round 4.
//  - k_gemm: coalesced gather (8 lanes per pixel-row), 512-thr CTA, N=256/CTA
//  - k_offset replaced by tensor-core GEMM (k_offmma) + k_params
// ---------------------------------------------------------------------------

#define HH 96
#define WW 96
#define SS 9216
#define NB 4
#define CIN 256
#define COUT 256
#define M_TOTAL (NB * SS)      // 36864
#define KDIM (9 * CIN)         // 2304
#define NKT 72                 // 2304/32

// Scratch
__device__ __align__(16) float g_xT[NB * SS * CIN];             // NHWC x
__device__ __align__(16) unsigned g_wF[144 * 2 * 8 * 32 * 8];   // main B frags
__device__ __align__(16) unsigned g_wOffF[144 * 2 * 32 * 8];    // offset B frags (N=32)
__device__ __align__(16) float g_om[27 * M_TOTAL];              // offset-conv output
__device__ __align__(16) float4 g_pw[9 * M_TOTAL];
__device__ __align__(16) int4   g_pi[9 * M_TOTAL];
__device__ float g_scale[COUT];
__device__ float g_shift[COUT];

// ---------------- asm helpers ----------------
__device__ __forceinline__ unsigned smem_u32(const void* p) {
    unsigned a;
    asm("{ .reg .u64 t; cvta.to.shared.u64 t, %1; cvt.u32.u64 %0, t; }" : "=r"(a) : "l"(p));
    return a;
}
#define LDSM_X4(r, a) \
    asm volatile("ldmatrix.sync.aligned.m8n8.x4.shared.b16 {%0,%1,%2,%3}, [%4];" \
                 : "=r"((r)[0]), "=r"((r)[1]), "=r"((r)[2]), "=r"((r)[3]) : "r"(a))
#define MMA_BF16(d, a, b) \
    asm volatile("mma.sync.aligned.m16n8k16.row.col.f32.bf16.bf16.f32 " \
                 "{%0,%1,%2,%3}, {%4,%5,%6,%7}, {%8,%9}, {%0,%1,%2,%3};" \
                 : "+f"((d)[0]), "+f"((d)[1]), "+f"((d)[2]), "+f"((d)[3]) \
                 : "r"((a)[0]), "r"((a)[1]), "r"((a)[2]), "r"((a)[3]), \
                   "r"((b)[0]), "r"((b)[1]))

__device__ __forceinline__ unsigned pack_bf16(float x0, float x1) {
    __nv_bfloat16 h0 = __float2bfloat16(x0);
    __nv_bfloat16 h1 = __float2bfloat16(x1);
    return (unsigned)__bfloat16_as_ushort(h0) | ((unsigned)__bfloat16_as_ushort(h1) << 16);
}

// ---------------------------------------------------------------------------
// K0: NCHW -> NHWC transpose
// ---------------------------------------------------------------------------
__global__ void k_transpose(const float* __restrict__ x) {
    __shared__ float tile[32][33];
    const int n  = blockIdx.z;
    const int c0 = blockIdx.y * 32;
    const int s0 = blockIdx.x * 32;
    const int tx = threadIdx.x, ty = threadIdx.y;
    const float* src = x + (size_t)n * CIN * SS;
#pragma unroll
    for (int i = 0; i < 32; i += 8)
        tile[ty + i][tx] = src[(size_t)(c0 + ty + i) * SS + (s0 + tx)];
    __syncthreads();
    float* dst = g_xT + (size_t)n * SS * CIN;
#pragma unroll
    for (int i = 0; i < 32; i += 8)
        dst[(size_t)(s0 + ty + i) * CIN + (c0 + tx)] = tile[tx][ty + i];
}

// ---------------------------------------------------------------------------
// K0b: main-GEMM B fragments (bf16 hi/lo), mma.sync col layout.
// ---------------------------------------------------------------------------
__global__ void k_wprep(const float* __restrict__ w) {
    const int T = blockIdx.x * 256 + threadIdx.x;
    const int r  = T & 7;
    const int l  = (T >> 3) & 31;
    const int cb = (T >> 8) & 7;
    const int s  = (T >> 11) & 1;
    const int K  = T >> 12;
    const int f  = r >> 1, rr = r & 1;
    const int n  = cb * 32 + f * 8 + (l >> 2);
    const int kk = K * 16 + (l & 3) * 2 + rr * 8;
    float v0, v1;
    {
        int tap = kk >> 8, c = kk & 255;
        v0 = w[(size_t)n * KDIM + c * 9 + tap];
        tap = (kk + 1) >> 8; c = (kk + 1) & 255;
        v1 = w[(size_t)n * KDIM + c * 9 + tap];
    }
    float h0 = __bfloat162float(__float2bfloat16(v0));
    float h1 = __bfloat162float(__float2bfloat16(v1));
    g_wF[T] = (s == 0) ? pack_bf16(h0, h1) : pack_bf16(v0 - h0, v1 - h1);
}

// ---------------------------------------------------------------------------
// K0c: offset-conv B fragments, N=32 (27 real, rest zero).
// index ((K*2+s)*32 + l)*8 + r,  r=f*2+rr, f 0..3 -> n = f*8+(l>>2)
// ---------------------------------------------------------------------------
__global__ void k_woffprep(const float* __restrict__ w_off) {
    const int T = blockIdx.x * 256 + threadIdx.x;   // 0..73727
    const int r = T & 7;
    const int l = (T >> 3) & 31;
    const int s = (T >> 8) & 1;
    const int K = T >> 9;                            // 0..143
    const int f = r >> 1, rr = r & 1;
    const int n = f * 8 + (l >> 2);
    const int kk = K * 16 + (l & 3) * 2 + rr * 8;
    float v0 = 0.0f, v1 = 0.0f;
    if (n < 27) {
        int tap = kk >> 8, c = kk & 255;
        v0 = w_off[((size_t)n * 256 + c) * 9 + tap];
        tap = (kk + 1) >> 8; c = (kk + 1) & 255;
        v1 = w_off[((size_t)n * 256 + c) * 9 + tap];
    }
    float h0 = __bfloat162float(__float2bfloat16(v0));
    float h1 = __bfloat162float(__float2bfloat16(v1));
    g_wOffF[T] = (s == 0) ? pack_bf16(h0, h1) : pack_bf16(v0 - h0, v1 - h1);
}

// ---------------------------------------------------------------------------
// K1: offset conv as HMMA GEMM. M=36864, N=32, K=2304, bf16x3.
// 512 thr = 16 warps: 8 m-warps (16 rows) x 2 n-warps (16 cols).
// A = im2col of x (contiguous rows, coalesced), double-buffered smem.
// ---------------------------------------------------------------------------
__global__ __launch_bounds__(512, 2) void k_offmma(const float* __restrict__ b_off) {
    __shared__ __nv_bfloat16 Asm[2][2][128][40];

    const int tid = threadIdx.x;
    const int wid = tid >> 5;
    const int lane = tid & 31;
    const int wm = wid >> 1;            // 0..7
    const int wn = wid & 1;             // 0..1
    const int m0 = blockIdx.x * 128;

    // gather role: 2 slots, 8 lanes per pixel-row chunk group
    int ph[2], pw_[2], pn[2], cpos[2];
#pragma unroll
    for (int s = 0; s < 2; s++) {
        int g = s * 512 + tid;
        int pg = g >> 3;
        cpos[s] = g & 7;
        int P = m0 + pg;
        pn[s] = P / SS;
        int rem = P % SS;
        ph[s] = rem / WW;
        pw_[s] = rem % WW;
    }

    const int lr = (lane & 7) + ((lane >> 3) & 1) * 8;
    const int lc = (lane >> 4) * 16;
    const unsigned Abase = smem_u32(&Asm[0][0][0][0]);

    float acc[2][4];
#pragma unroll
    for (int f = 0; f < 2; f++)
#pragma unroll
        for (int c = 0; c < 4; c++) acc[f][c] = 0.0f;

    auto gather = [&](int t, int buf) {
        const int tap = t >> 3, sub = t & 7;
        const int ky = tap / 3 - 1, kx = tap % 3 - 1;
#pragma unroll
        for (int s = 0; s < 2; s++) {
            const int g = s * 512 + tid;
            const int pg = g >> 3;
            const int y = ph[s] + ky, x = pw_[s] + kx;
            float4 v = make_float4(0, 0, 0, 0);
            if (y >= 0 && y < HH && x >= 0 && x < WW)
                v = *(const float4*)(g_xT + ((size_t)(pn[s] * SS + y * WW + x) * CIN
                                             + sub * 32 + cpos[s] * 4));
            float h0 = __bfloat162float(__float2bfloat16(v.x));
            float h1 = __bfloat162float(__float2bfloat16(v.y));
            float h2 = __bfloat162float(__float2bfloat16(v.z));
            float h3 = __bfloat162float(__float2bfloat16(v.w));
            *(uint2*)&Asm[buf][0][pg][cpos[s] * 4] =
                make_uint2(pack_bf16(h0, h1), pack_bf16(h2, h3));
            *(uint2*)&Asm[buf][1][pg][cpos[s] * 4] =
                make_uint2(pack_bf16(v.x - h0, v.y - h1), pack_bf16(v.z - h2, v.w - h3));
        }
    };

    auto compute = [&](int t, int buf) {
        const unsigned base0 = Abase + (unsigned)(buf * 2) * (128 * 40 * 2);
        const unsigned base1 = base0 + 128 * 40 * 2;
#pragma unroll
        for (int q = 0; q < 2; q++) {
            const int K = t * 2 + q;
            uint4 bh = *(const uint4*)(g_wOffF + ((size_t)(K * 2 + 0) * 32 + lane) * 8 + wn * 4);
            uint4 bl = *(const uint4*)(g_wOffF + ((size_t)(K * 2 + 1) * 32 + lane) * 8 + wn * 4);
            unsigned Bh[4] = {bh.x, bh.y, bh.z, bh.w};
            unsigned Bl[4] = {bl.x, bl.y, bl.z, bl.w};
            const unsigned ro = (unsigned)(wm * 16 + lr) * 80 + q * 32 + lc;
            unsigned ah[4], al[4];
            LDSM_X4(ah, base0 + ro);
            LDSM_X4(al, base1 + ro);
#pragma unroll
            for (int f = 0; f < 2; f++) {
                MMA_BF16(acc[f], ah, &Bh[2 * f]);
                MMA_BF16(acc[f], ah, &Bl[2 * f]);
                MMA_BF16(acc[f], al, &Bh[2 * f]);
            }
        }
    };

    gather(0, 0);
    __syncthreads();
#pragma unroll 1
    for (int t = 0; t < NKT; t++) {
        if (t + 1 < NKT) gather(t + 1, (t + 1) & 1);
        compute(t, t & 1);
        __syncthreads();
    }

    // write om (27 channels) + b_off
    const int r0 = m0 + wm * 16 + (lane >> 2);
#pragma unroll
    for (int f = 0; f < 2; f++) {
        const int c0 = wn * 16 + f * 8 + (lane & 3) * 2;
#pragma unroll
        for (int cc = 0; cc < 2; cc++) {
            const int c = c0 + cc;
            if (c < 27) {
                const float bo = __ldg(&b_off[c]);
                g_om[(size_t)c * M_TOTAL + r0]     = acc[f][cc]     + bo;
                g_om[(size_t)c * M_TOTAL + r0 + 8] = acc[f][cc + 2] + bo;
            }
        }
    }
}

// ---------------------------------------------------------------------------
// K1b: bilinear parameter precompute from om
// ---------------------------------------------------------------------------
__global__ void k_params(int dummy) {
    const int p = blockIdx.x * 256 + threadIdx.x;
    const int rem = p % SS;
    const int h = rem / WW, w = rem % WW;
    float om[27];
#pragma unroll
    for (int k = 0; k < 27; k++) om[k] = g_om[(size_t)k * M_TOTAL + p];
#pragma unroll
    for (int k = 0; k < 9; k++) {
        float dy = om[k];
        float dx = om[9 + k];
        float mm = 1.0f / (1.0f + __expf(-om[18 + k]));
        float py = (dy + (float)h) + (float)(k / 3 - 1);
        float px = (dx + (float)w) + (float)(k % 3 - 1);
        float y0f = floorf(py), x0f = floorf(px);
        float ly = py - y0f, lx = px - x0f;
        float vy0 = (y0f >= 0.0f && y0f <= 95.0f) ? 1.0f : 0.0f;
        float vy1 = (y0f + 1.0f >= 0.0f && y0f + 1.0f <= 95.0f) ? 1.0f : 0.0f;
        float vx0 = (x0f >= 0.0f && x0f <= 95.0f) ? 1.0f : 0.0f;
        float vx1 = (x0f + 1.0f >= 0.0f && x0f + 1.0f <= 95.0f) ? 1.0f : 0.0f;
        int iy0 = (int)fminf(fmaxf(y0f, 0.0f), 95.0f);
        int iy1 = (int)fminf(fmaxf(y0f + 1.0f, 0.0f), 95.0f);
        int ix0 = (int)fminf(fmaxf(x0f, 0.0f), 95.0f);
        int ix1 = (int)fminf(fmaxf(x0f + 1.0f, 0.0f), 95.0f);
        float w00 = (1.0f - ly) * (1.0f - lx) * vy0 * vx0 * mm;
        float w01 = (1.0f - ly) * lx          * vy0 * vx1 * mm;
        float w10 = ly          * (1.0f - lx) * vy1 * vx0 * mm;
        float w11 = ly          * lx          * vy1 * vx1 * mm;
        g_pw[k * M_TOTAL + p] = make_float4(w00, w01, w10, w11);
        g_pi[k * M_TOTAL + p] = make_int4(iy0 * WW + ix0, iy0 * WW + ix1,
                                          iy1 * WW + ix0, iy1 * WW + ix1);
    }
}

// ---------------------------------------------------------------------------
// K2: main HMMA GEMM, bf16x3. Mtile=128, N=256 in ONE CTA (512 thr, 16 warps:
// 2 m-warps x 8 n-warps, warp tile 64x32). Coalesced gather: 8 lanes cover one
// 128B pixel-corner row.
// ---------------------------------------------------------------------------
__global__ __launch_bounds__(512, 1) void k_gemm(const float* __restrict__ bvec,
                                                 float* __restrict__ out) {
    __shared__ __nv_bfloat16 Asm[2][2][128][40];   // 40KB

    const int tid = threadIdx.x;
    const int wid = tid >> 5;
    const int lane = tid & 31;
    const int wm = wid >> 3;            // 0..1
    const int wn = wid & 7;             // 0..7

    const int m0 = blockIdx.x * 128;
    const int n = m0 / SS;
    const int sb = m0 % SS;
    const float* xbase = g_xT + (size_t)n * SS * CIN;

    // gather role: slot s -> chunk g = s*512+tid; pixel g>>3, 16B chunk g&7
    const int pg0 = tid >> 3;           // slot0 pixel (0..63)
    const int pg1 = 64 + pg0;           // slot1 pixel
    const int cp = tid & 7;

    const int lr = (lane & 7) + ((lane >> 3) & 1) * 8;
    const int lc = (lane >> 4) * 16;
    const unsigned Abase = smem_u32(&Asm[0][0][0][0]);

    float acc[4][4][4];
#pragma unroll
    for (int a = 0; a < 4; a++)
#pragma unroll
        for (int b = 0; b < 4; b++)
#pragma unroll
            for (int c = 0; c < 4; c++) acc[a][b][c] = 0.0f;

    float4 pm[2];
    int4 ii[2];

    auto gather = [&](int t, int buf) {
        const int tap = t >> 3, sub = t & 7;
        if (sub == 0) {
            pm[0] = g_pw[tap * M_TOTAL + m0 + pg0];
            ii[0] = g_pi[tap * M_TOTAL + m0 + pg0];
            pm[1] = g_pw[tap * M_TOTAL + m0 + pg1];
            ii[1] = g_pi[tap * M_TOTAL + m0 + pg1];
        }
        const int cb = sub * 32 + cp * 4;
#pragma unroll
        for (int s = 0; s < 2; s++) {
            const float4 w4 = pm[s];
            float4 v00 = *(const float4*)(xbase + (size_t)ii[s].x * CIN + cb);
            float4 v01 = *(const float4*)(xbase + (size_t)ii[s].y * CIN + cb);
            float4 v10 = *(const float4*)(xbase + (size_t)ii[s].z * CIN + cb);
            float4 v11 = *(const float4*)(xbase + (size_t)ii[s].w * CIN + cb);
            float a0 = w4.x * v00.x + w4.y * v01.x + w4.z * v10.x + w4.w * v11.x;
            float a1 = w4.x * v00.y + w4.y * v01.y + w4.z * v10.y + w4.w * v11.y;
            float a2 = w4.x * v00.z + w4.y * v01.z + w4.z * v10.z + w4.w * v11.z;
            float a3 = w4.x * v00.w + w4.y * v01.w + w4.z * v10.w + w4.w * v11.w;
            float h0 = __bfloat162float(__float2bfloat16(a0));
            float h1 = __bfloat162float(__float2bfloat16(a1));
            float h2 = __bfloat162float(__float2bfloat16(a2));
            float h3 = __bfloat162float(__float2bfloat16(a3));
            const int pg = s ? pg1 : pg0;
            *(uint2*)&Asm[buf][0][pg][cp * 4] =
                make_uint2(pack_bf16(h0, h1), pack_bf16(h2, h3));
            *(uint2*)&Asm[buf][1][pg][cp * 4] =
                make_uint2(pack_bf16(a0 - h0, a1 - h1), pack_bf16(a2 - h2, a3 - h3));
        }
    };

    auto compute = [&](int t, int buf) {
        const unsigned base0 = Abase + (unsigned)(buf * 2) * (128 * 40 * 2);
        const unsigned base1 = base0 + 128 * 40 * 2;
#pragma unroll
        for (int q = 0; q < 2; q++) {
            const int K = t * 2 + q;
            const uint4* bph = (const uint4*)(g_wF + (((size_t)(K * 2 + 0) * 8 + wn) * 32 + lane) * 8);
            const uint4* bpl = (const uint4*)(g_wF + (((size_t)(K * 2 + 1) * 8 + wn) * 32 + lane) * 8);
            uint4 h0 = bph[0], h1 = bph[1];
            uint4 l0 = bpl[0], l1 = bpl[1];
            unsigned Bh[8] = {h0.x, h0.y, h0.z, h0.w, h1.x, h1.y, h1.z, h1.w};
            unsigned Bl[8] = {l0.x, l0.y, l0.z, l0.w, l1.x, l1.y, l1.z, l1.w};
#pragma unroll
            for (int mt = 0; mt < 4; mt++) {
                const unsigned ro = (unsigned)(wm * 64 + mt * 16 + lr) * 80 + q * 32 + lc;
                unsigned ah[4], al[4];
                LDSM_X4(ah, base0 + ro);
                LDSM_X4(al, base1 + ro);
#pragma unroll
                for (int f = 0; f < 4; f++) {
                    MMA_BF16(acc[mt][f], ah, &Bh[2 * f]);
                    MMA_BF16(acc[mt][f], ah, &Bl[2 * f]);
                    MMA_BF16(acc[mt][f], al, &Bh[2 * f]);
                }
            }
        }
    };

    gather(0, 0);
    __syncthreads();
#pragma unroll 1
    for (int t = 0; t < NKT; t++) {
        if (t + 1 < NKT) gather(t + 1, (t + 1) & 1);
        compute(t, t & 1);
        __syncthreads();
    }

    // epilogue: +bias, write pre-BN y
#pragma unroll
    for (int f = 0; f < 4; f++) {
        const int co = wn * 32 + f * 8 + (lane & 3) * 2;
        const float b0 = __ldg(&bvec[co]);
        const float b1 = __ldg(&bvec[co + 1]);
        float* o0 = out + ((size_t)n * COUT + co) * SS + sb + wm * 64 + (lane >> 2);
        float* o1 = o0 + SS;
#pragma unroll
        for (int mt = 0; mt < 4; mt++) {
            const int r = mt * 16;
            o0[r]     = acc[mt][f][0] + b0;
            o1[r]     = acc[mt][f][1] + b1;
            o0[r + 8] = acc[mt][f][2] + b0;
            o1[r + 8] = acc[mt][f][3] + b1;
        }
    }
}

// ---------------------------------------------------------------------------
// K3: BN statistics
// ---------------------------------------------------------------------------
__global__ void k_stats(const float* __restrict__ y, const float* __restrict__ gamma,
                        const float* __restrict__ beta) {
    const int co = blockIdx.x;
    const int t = threadIdx.x;
    float s = 0.0f, q = 0.0f;
#pragma unroll
    for (int n = 0; n < NB; n++) {
        const float* p = y + ((size_t)n * COUT + co) * SS;
#pragma unroll
        for (int i = 0; i < 9; i++) {
            float4 v = *(const float4*)(p + t * 4 + i * 1024);
            s += v.x + v.y + v.z + v.w;
            q += v.x * v.x + v.y * v.y + v.z * v.z + v.w * v.w;
        }
    }
#pragma unroll
    for (int o = 16; o; o >>= 1) {
        s += __shfl_xor_sync(~0u, s, o);
        q += __shfl_xor_sync(~0u, q, o);
    }
    __shared__ float ssm[8], qsm[8];
    if ((t & 31) == 0) { ssm[t >> 5] = s; qsm[t >> 5] = q; }
    __syncthreads();
    if (t == 0) {
        s = 0.0f; q = 0.0f;
#pragma unroll
        for (int i = 0; i < 8; i++) { s += ssm[i]; q += qsm[i]; }
        float mean = s / (float)M_TOTAL;
        float var = q / (float)M_TOTAL - mean * mean;
        float sc = gamma[co] * rsqrtf(var + 1e-5f);
        g_scale[co] = sc;
        g_shift[co] = beta[co] - mean * sc;
    }
}

// ---------------------------------------------------------------------------
// K4: normalize + ReLU in place
// ---------------------------------------------------------------------------
__global__ void k_norm(float* __restrict__ out) {
    const size_t i = ((size_t)blockIdx.x * blockDim.x + threadIdx.x) * 4;
    const int co = (int)((i / SS) & 255);
    float sc = g_scale[co], sh = g_shift[co];
    float4 v = *(float4*)(out + i);
    v.x = fmaxf(v.x * sc + sh, 0.0f);
    v.y = fmaxf(v.y * sc + sh, 0.0f);
    v.z = fmaxf(v.z * sc + sh, 0.0f);
    v.w = fmaxf(v.w * sc + sh, 0.0f);
    *(float4*)(out + i) = v;
}

// ---------------------------------------------------------------------------
extern "C" void kernel_launch(void* const* d_in, const int* in_sizes, int n_in,
                              void* d_out, int out_size) {
    (void)in_sizes; (void)n_in; (void)out_size;
    const float* x     = (const float*)d_in[0];
    const float* w_off = (const float*)d_in[1];
    const float* b_off = (const float*)d_in[2];
    const float* w     = (const float*)d_in[3];
    const float* b     = (const float*)d_in[4];
    const float* gamma = (const float*)d_in[5];
    const float* beta  = (const float*)d_in[6];
    float* out = (float*)d_out;

    k_transpose<<<dim3(SS / 32, CIN / 32, NB), dim3(32, 8)>>>(x);
    k_wprep<<<2304, 256>>>(w);
    k_woffprep<<<288, 256>>>(w_off);
    k_offmma<<<M_TOTAL / 128, 512>>>(b_off);
    k_params<<<M_TOTAL / 256, 256>>>(0);
    k_gemm<<<M_TOTAL / 128, 512>>>(b, out);
    k_stats<<<COUT, 256>>>(out, gamma, beta);
    k_norm<<<(NB * COUT * SS) / (256 * 4), 256>>>(out);
}

// round 5
// speedup vs baseline: 4.1979x; 1.2793x over previous
#include <cuda_runtime.h>
#include <cuda_bf16.h>

// ---------------------------------------------------------------------------
// DeformConv fused pipeline, round 5: single-pass TF32 mma (m16n8k8).
// ---------------------------------------------------------------------------

#define HH 96
#define WW 96
#define SS 9216
#define NB 4
#define CIN 256
#define COUT 256
#define M_TOTAL (NB * SS)      // 36864
#define KDIM (9 * CIN)         // 2304
#define NKT 72                 // k32 tiles

// Scratch
__device__ __align__(16) float g_xT[NB * SS * CIN];        // NHWC x
__device__ __align__(16) uint4 g_wFa[288 * 8 * 32];        // main B frags f0,f1
__device__ __align__(16) uint4 g_wFb[288 * 8 * 32];        // main B frags f2,f3
__device__ __align__(16) uint4 g_wOffF[288 * 2 * 32];      // offset B frags
__device__ __align__(16) float g_om[27 * M_TOTAL];
__device__ __align__(16) float4 g_pw[9 * M_TOTAL];
__device__ __align__(16) int4   g_pi[9 * M_TOTAL];
__device__ float g_chsum[COUT];
__device__ float g_chsq[COUT];
__device__ float g_scale[COUT];
__device__ float g_shift[COUT];

// ---------------- asm helpers ----------------
#define MMA_TF32(d, a, bx, by) \
    asm volatile("mma.sync.aligned.m16n8k8.row.col.f32.tf32.tf32.f32 " \
                 "{%0,%1,%2,%3},{%4,%5,%6,%7},{%8,%9},{%0,%1,%2,%3};" \
                 : "+f"((d)[0]), "+f"((d)[1]), "+f"((d)[2]), "+f"((d)[3]) \
                 : "r"((a)[0]), "r"((a)[1]), "r"((a)[2]), "r"((a)[3]), \
                   "r"(bx), "r"(by))

__device__ __forceinline__ unsigned f2tf(float f) {
    unsigned u;
    asm("cvt.rna.tf32.f32 %0, %1;" : "=r"(u) : "f"(f));
    return u;
}

// ---------------------------------------------------------------------------
// K0: NCHW -> NHWC transpose
// ---------------------------------------------------------------------------
__global__ void k_transpose(const float* __restrict__ x) {
    __shared__ float tile[32][33];
    const int n  = blockIdx.z;
    const int c0 = blockIdx.y * 32;
    const int s0 = blockIdx.x * 32;
    const int tx = threadIdx.x, ty = threadIdx.y;
    const float* src = x + (size_t)n * CIN * SS;
#pragma unroll
    for (int i = 0; i < 32; i += 8)
        tile[ty + i][tx] = src[(size_t)(c0 + ty + i) * SS + (s0 + tx)];
    __syncthreads();
    float* dst = g_xT + (size_t)n * SS * CIN;
#pragma unroll
    for (int i = 0; i < 32; i += 8)
        dst[(size_t)(s0 + ty + i) * CIN + (c0 + tx)] = tile[tx][ty + i];
}

// ---------------------------------------------------------------------------
// K0b: main-GEMM B fragments, tf32, mma.sync m16n8k8 col layout.
// ktile t: tap = t>>3, channels (t&7)*32..+31. K8 = t*4+q.
// g_wFa[(K8*8+cb)*32+lane] = {f0.b0, f0.b1, f1.b0, f1.b1}; g_wFb: f2,f3.
// n = cb*32 + f*8 + (lane>>2); b0: c = cbase + (lane&3), b1: c + 4.
// Also zeroes BN accumulators (runs before k_gemm every launch).
// ---------------------------------------------------------------------------
__global__ void k_wprep(const float* __restrict__ w) {
    const int T = blockIdx.x * 256 + threadIdx.x;   // 0..73727
    if (blockIdx.x == 0 && threadIdx.x < 256) {
        g_chsum[threadIdx.x] = 0.0f;
        g_chsq[threadIdx.x] = 0.0f;
    }
    const int lane = T & 31;
    const int cb = (T >> 5) & 7;
    const int K8 = T >> 8;                           // 0..287
    const int t = K8 >> 2;
    const int tap = t >> 3;
    const int c0 = (t & 7) * 32 + (K8 & 3) * 8 + (lane & 3);
    const int c1 = c0 + 4;
    unsigned r[8];
#pragma unroll
    for (int f = 0; f < 4; f++) {
        const int n = cb * 32 + f * 8 + (lane >> 2);
        r[2 * f]     = f2tf(w[((size_t)n * 256 + c0) * 9 + tap]);
        r[2 * f + 1] = f2tf(w[((size_t)n * 256 + c1) * 9 + tap]);
    }
    g_wFa[(K8 * 8 + cb) * 32 + lane] = make_uint4(r[0], r[1], r[2], r[3]);
    g_wFb[(K8 * 8 + cb) * 32 + lane] = make_uint4(r[4], r[5], r[6], r[7]);
}

// ---------------------------------------------------------------------------
// K0c: offset-conv B fragments (N=32: 27 real + zero pad).
// g_wOffF[(K8*2+wn)*32+lane] = {f0.b0, f0.b1, f1.b0, f1.b1},
// n = wn*16 + fl*8 + (lane>>2).
// ---------------------------------------------------------------------------
__global__ void k_woffprep(const float* __restrict__ w_off) {
    const int T = blockIdx.x * 256 + threadIdx.x;   // 0..18431
    const int lane = T & 31;
    const int wn = (T >> 5) & 1;
    const int K8 = T >> 6;                           // 0..287
    const int t = K8 >> 2;
    const int tap = t >> 3;
    const int c0 = (t & 7) * 32 + (K8 & 3) * 8 + (lane & 3);
    const int c1 = c0 + 4;
    unsigned r[4];
#pragma unroll
    for (int fl = 0; fl < 2; fl++) {
        const int n = wn * 16 + fl * 8 + (lane >> 2);
        float v0 = 0.0f, v1 = 0.0f;
        if (n < 27) {
            v0 = w_off[((size_t)n * 256 + c0) * 9 + tap];
            v1 = w_off[((size_t)n * 256 + c1) * 9 + tap];
        }
        r[2 * fl]     = f2tf(v0);
        r[2 * fl + 1] = f2tf(v1);
    }
    g_wOffF[(K8 * 2 + wn) * 32 + lane] = make_uint4(r[0], r[1], r[2], r[3]);
}

// ---------------------------------------------------------------------------
// K1: offset conv as tf32 GEMM. M=36864, N=32, K=2304.
// 512 thr: 8 m-warps x 2 n-warps. A = im2col (coalesced copy + tf32 cvt).
// ---------------------------------------------------------------------------
__global__ __launch_bounds__(512, 2) void k_offmma(const float* __restrict__ b_off) {
    __shared__ unsigned Asm[2][128][36];   // 36.9KB

    const int tid = threadIdx.x;
    const int wid = tid >> 5;
    const int lane = tid & 31;
    const int wm = wid >> 1;            // 0..7
    const int wn = wid & 1;             // 0..1
    const int m0 = blockIdx.x * 128;

    // gather: slot s -> pixel (s*512+tid)>>3, 16B chunk tid&7
    const int pg0 = tid >> 3, pg1 = 64 + pg0;
    const int cp = tid & 7;
    int ph[2], pw_[2], pn[2];
#pragma unroll
    for (int s = 0; s < 2; s++) {
        const int P = m0 + (s ? pg1 : pg0);
        pn[s] = P / SS;
        const int rem = P % SS;
        ph[s] = rem / WW;
        pw_[s] = rem % WW;
    }

    float acc[2][4];
#pragma unroll
    for (int f = 0; f < 2; f++)
#pragma unroll
        for (int c = 0; c < 4; c++) acc[f][c] = 0.0f;

    auto gather = [&](int t, int buf) {
        const int tap = t >> 3, sub = t & 7;
        const int ky = tap / 3 - 1, kx = tap % 3 - 1;
        const int cb = sub * 32 + cp * 4;
#pragma unroll
        for (int s = 0; s < 2; s++) {
            const int y = ph[s] + ky, x = pw_[s] + kx;
            float4 v = make_float4(0, 0, 0, 0);
            if (y >= 0 && y < HH && x >= 0 && x < WW)
                v = *(const float4*)(g_xT + ((size_t)(pn[s] * SS + y * WW + x) * CIN + cb));
            *(uint4*)&Asm[buf][s ? pg1 : pg0][cp * 4] =
                make_uint4(f2tf(v.x), f2tf(v.y), f2tf(v.z), f2tf(v.w));
        }
    };

    auto compute = [&](int t, int buf) {
#pragma unroll
        for (int q = 0; q < 4; q++) {
            const uint4 B = g_wOffF[(((size_t)t * 4 + q) * 2 + wn) * 32 + lane];
            const int r = wm * 16 + (lane >> 2);
            const int c = q * 8 + (lane & 3);
            unsigned a[4];
            a[0] = Asm[buf][r][c];
            a[1] = Asm[buf][r + 8][c];
            a[2] = Asm[buf][r][c + 4];
            a[3] = Asm[buf][r + 8][c + 4];
            MMA_TF32(acc[0], a, B.x, B.y);
            MMA_TF32(acc[1], a, B.z, B.w);
        }
    };

    gather(0, 0);
    __syncthreads();
#pragma unroll 1
    for (int t = 0; t < NKT; t++) {
        if (t + 1 < NKT) gather(t + 1, (t + 1) & 1);
        compute(t, t & 1);
        __syncthreads();
    }

    const int r0 = m0 + wm * 16 + (lane >> 2);
#pragma unroll
    for (int f = 0; f < 2; f++) {
        const int c0 = wn * 16 + f * 8 + (lane & 3) * 2;
#pragma unroll
        for (int cc = 0; cc < 2; cc++) {
            const int c = c0 + cc;
            if (c < 27) {
                const float bo = __ldg(&b_off[c]);
                g_om[(size_t)c * M_TOTAL + r0]     = acc[f][cc]     + bo;
                g_om[(size_t)c * M_TOTAL + r0 + 8] = acc[f][cc + 2] + bo;
            }
        }
    }
}

// ---------------------------------------------------------------------------
// K1b: bilinear parameter precompute from om
// ---------------------------------------------------------------------------
__global__ void k_params(int dummy) {
    const int p = blockIdx.x * 256 + threadIdx.x;
    const int rem = p % SS;
    const int h = rem / WW, w = rem % WW;
    float om[27];
#pragma unroll
    for (int k = 0; k < 27; k++) om[k] = g_om[(size_t)k * M_TOTAL + p];
#pragma unroll
    for (int k = 0; k < 9; k++) {
        float dy = om[k];
        float dx = om[9 + k];
        float mm = 1.0f / (1.0f + __expf(-om[18 + k]));
        float py = (dy + (float)h) + (float)(k / 3 - 1);
        float px = (dx + (float)w) + (float)(k % 3 - 1);
        float y0f = floorf(py), x0f = floorf(px);
        float ly = py - y0f, lx = px - x0f;
        float vy0 = (y0f >= 0.0f && y0f <= 95.0f) ? 1.0f : 0.0f;
        float vy1 = (y0f + 1.0f >= 0.0f && y0f + 1.0f <= 95.0f) ? 1.0f : 0.0f;
        float vx0 = (x0f >= 0.0f && x0f <= 95.0f) ? 1.0f : 0.0f;
        float vx1 = (x0f + 1.0f >= 0.0f && x0f + 1.0f <= 95.0f) ? 1.0f : 0.0f;
        int iy0 = (int)fminf(fmaxf(y0f, 0.0f), 95.0f);
        int iy1 = (int)fminf(fmaxf(y0f + 1.0f, 0.0f), 95.0f);
        int ix0 = (int)fminf(fmaxf(x0f, 0.0f), 95.0f);
        int ix1 = (int)fminf(fmaxf(x0f + 1.0f, 0.0f), 95.0f);
        float w00 = (1.0f - ly) * (1.0f - lx) * vy0 * vx0 * mm;
        float w01 = (1.0f - ly) * lx          * vy0 * vx1 * mm;
        float w10 = ly          * (1.0f - lx) * vy1 * vx0 * mm;
        float w11 = ly          * lx          * vy1 * vx1 * mm;
        g_pw[k * M_TOTAL + p] = make_float4(w00, w01, w10, w11);
        g_pi[k * M_TOTAL + p] = make_int4(iy0 * WW + ix0, iy0 * WW + ix1,
                                          iy1 * WW + ix0, iy1 * WW + ix1);
    }
}

// ---------------------------------------------------------------------------
// K2: main tf32 GEMM. Mtile=128, Ntile=256, Ktile=32. 512 thr (16 warps:
// 2 m-warps x 8 n-warps, warp tile 64x32). Fused BN partial sums.
// ---------------------------------------------------------------------------
__global__ __launch_bounds__(512, 1) void k_gemm(const float* __restrict__ bvec,
                                                 float* __restrict__ out) {
    __shared__ unsigned Asm[2][128][36];   // 36.9KB (reused for BN transpose)

    const int tid = threadIdx.x;
    const int wid = tid >> 5;
    const int lane = tid & 31;
    const int wm = wid >> 3;            // 0..1
    const int wn = wid & 7;             // 0..7

    const int m0 = blockIdx.x * 128;
    const int n = m0 / SS;
    const int sb = m0 % SS;
    const float* xbase = g_xT + (size_t)n * SS * CIN;

    const int pg0 = tid >> 3, pg1 = 64 + pg0;
    const int cp = tid & 7;

    float acc[4][4][4];
#pragma unroll
    for (int a = 0; a < 4; a++)
#pragma unroll
        for (int b = 0; b < 4; b++)
#pragma unroll
            for (int c = 0; c < 4; c++) acc[a][b][c] = 0.0f;

    float4 pm[2];
    int4 ii[2];

    auto gather = [&](int t, int buf) {
        const int tap = t >> 3, sub = t & 7;
        if (sub == 0) {
            pm[0] = g_pw[tap * M_TOTAL + m0 + pg0];
            ii[0] = g_pi[tap * M_TOTAL + m0 + pg0];
            pm[1] = g_pw[tap * M_TOTAL + m0 + pg1];
            ii[1] = g_pi[tap * M_TOTAL + m0 + pg1];
        }
        const int cb = sub * 32 + cp * 4;
#pragma unroll
        for (int s = 0; s < 2; s++) {
            const float4 w4 = pm[s];
            float4 v00 = *(const float4*)(xbase + (size_t)ii[s].x * CIN + cb);
            float4 v01 = *(const float4*)(xbase + (size_t)ii[s].y * CIN + cb);
            float4 v10 = *(const float4*)(xbase + (size_t)ii[s].z * CIN + cb);
            float4 v11 = *(const float4*)(xbase + (size_t)ii[s].w * CIN + cb);
            float a0 = w4.x * v00.x + w4.y * v01.x + w4.z * v10.x + w4.w * v11.x;
            float a1 = w4.x * v00.y + w4.y * v01.y + w4.z * v10.y + w4.w * v11.y;
            float a2 = w4.x * v00.z + w4.y * v01.z + w4.z * v10.z + w4.w * v11.z;
            float a3 = w4.x * v00.w + w4.y * v01.w + w4.z * v10.w + w4.w * v11.w;
            *(uint4*)&Asm[buf][s ? pg1 : pg0][cp * 4] =
                make_uint4(f2tf(a0), f2tf(a1), f2tf(a2), f2tf(a3));
        }
    };

    auto compute = [&](int t, int buf) {
#pragma unroll
        for (int q = 0; q < 4; q++) {
            const size_t bi = (((size_t)t * 4 + q) * 8 + wn) * 32 + lane;
            const uint4 Ba = g_wFa[bi];
            const uint4 Bb = g_wFb[bi];
#pragma unroll
            for (int mt = 0; mt < 4; mt++) {
                const int r = wm * 64 + mt * 16 + (lane >> 2);
                const int c = q * 8 + (lane & 3);
                unsigned a[4];
                a[0] = Asm[buf][r][c];
                a[1] = Asm[buf][r + 8][c];
                a[2] = Asm[buf][r][c + 4];
                a[3] = Asm[buf][r + 8][c + 4];
                MMA_TF32(acc[mt][0], a, Ba.x, Ba.y);
                MMA_TF32(acc[mt][1], a, Ba.z, Ba.w);
                MMA_TF32(acc[mt][2], a, Bb.x, Bb.y);
                MMA_TF32(acc[mt][3], a, Bb.z, Bb.w);
            }
        }
    };

    gather(0, 0);
    __syncthreads();
#pragma unroll 1
    for (int t = 0; t < NKT; t++) {
        if (t + 1 < NKT) gather(t + 1, (t + 1) & 1);
        compute(t, t & 1);
        __syncthreads();
    }

    // epilogue: +bias, write pre-BN y, per-thread BN partials
    float* Ssm = (float*)&Asm[0][0][0];          // [256][16]
    float* Qsm = Ssm + 4096;                     // [256][16]
    const int slot = wm * 8 + (lane >> 2);
#pragma unroll
    for (int f = 0; f < 4; f++) {
        const int co = wn * 32 + f * 8 + (lane & 3) * 2;
        const float b0 = __ldg(&bvec[co]);
        const float b1 = __ldg(&bvec[co + 1]);
        float* o0 = out + ((size_t)n * COUT + co) * SS + sb + wm * 64 + (lane >> 2);
        float* o1 = o0 + SS;
        float s0 = 0, q0 = 0, s1 = 0, q1 = 0;
#pragma unroll
        for (int mt = 0; mt < 4; mt++) {
            const int r = mt * 16;
            float v;
            v = acc[mt][f][0] + b0; o0[r]     = v; s0 += v; q0 += v * v;
            v = acc[mt][f][1] + b1; o1[r]     = v; s1 += v; q1 += v * v;
            v = acc[mt][f][2] + b0; o0[r + 8] = v; s0 += v; q0 += v * v;
            v = acc[mt][f][3] + b1; o1[r + 8] = v; s1 += v; q1 += v * v;
        }
        Ssm[co * 16 + slot] = s0;  Ssm[(co + 1) * 16 + slot] = s1;
        Qsm[co * 16 + slot] = q0;  Qsm[(co + 1) * 16 + slot] = q1;
    }
    __syncthreads();
    if (tid < 256) {
        float s = 0;
#pragma unroll
        for (int j = 0; j < 16; j++) s += Ssm[tid * 16 + j];
        atomicAdd(&g_chsum[tid], s);
    } else {
        float s = 0;
#pragma unroll
        for (int j = 0; j < 16; j++) s += Qsm[(tid - 256) * 16 + j];
        atomicAdd(&g_chsq[tid - 256], s);
    }
}

// ---------------------------------------------------------------------------
// K3: finalize BN scale/shift
// ---------------------------------------------------------------------------
__global__ void k_stats(const float* __restrict__ gamma, const float* __restrict__ beta) {
    const int co = threadIdx.x;
    const float inv = 1.0f / (float)M_TOTAL;
    float mean = g_chsum[co] * inv;
    float var = g_chsq[co] * inv - mean * mean;
    float sc = gamma[co] * rsqrtf(var + 1e-5f);
    g_scale[co] = sc;
    g_shift[co] = beta[co] - mean * sc;
}

// ---------------------------------------------------------------------------
// K4: normalize + ReLU in place
// ---------------------------------------------------------------------------
__global__ void k_norm(float* __restrict__ out) {
    const size_t i = ((size_t)blockIdx.x * blockDim.x + threadIdx.x) * 4;
    const int co = (int)((i / SS) & 255);
    float sc = g_scale[co], sh = g_shift[co];
    float4 v = *(float4*)(out + i);
    v.x = fmaxf(v.x * sc + sh, 0.0f);
    v.y = fmaxf(v.y * sc + sh, 0.0f);
    v.z = fmaxf(v.z * sc + sh, 0.0f);
    v.w = fmaxf(v.w * sc + sh, 0.0f);
    *(float4*)(out + i) = v;
}

// ---------------------------------------------------------------------------
extern "C" void kernel_launch(void* const* d_in, const int* in_sizes, int n_in,
                              void* d_out, int out_size) {
    (void)in_sizes; (void)n_in; (void)out_size;
    const float* x     = (const float*)d_in[0];
    const float* w_off = (const float*)d_in[1];
    const float* b_off = (const float*)d_in[2];
    const float* w     = (const float*)d_in[3];
    const float* b     = (const float*)d_in[4];
    const float* gamma = (const float*)d_in[5];
    const float* beta  = (const float*)d_in[6];
    float* out = (float*)d_out;

    k_transpose<<<dim3(SS / 32, CIN / 32, NB), dim3(32, 8)>>>(x);
    k_wprep<<<288, 256>>>(w);
    k_woffprep<<<72, 256>>>(w_off);
    k_offmma<<<M_TOTAL / 128, 512>>>(b_off);
    k_params<<<M_TOTAL / 256, 256>>>(0);
    k_gemm<<<M_TOTAL / 128, 512>>>(b, out);
    k_stats<<<1, 256>>>(gamma, beta);
    k_norm<<<(NB * COUT * SS) / (256 * 4), 256>>>(out);
}